// round 7
// baseline (speedup 1.0000x reference)
#include <cuda_runtime.h>

#define BATCH 16
#define HDIM 512
#define WDIM 512
#define HW (HDIM * WDIM)
#define NTOT (BATCH * 3 * HW)          // 12,582,912 elements per tensor
#define NQ (NTOT / 4)                  // 3,145,728 float4-pairs
#define NBOX (BATCH * 32)              // 512 box blocks (batch x landmark)
#define NSTREAM 592
#define GRID (NBOX + NSTREAM)
#define THREADS 256

__device__ double       g_acc;
__device__ unsigned int g_count;

__global__ void __launch_bounds__(THREADS, 5)
fused_loss_kernel(const float* __restrict__ pred,
                  const float* __restrict__ targ,
                  const int*   __restrict__ lm,
                  float*       __restrict__ out) {
    __shared__ float s_warp[8];
    __shared__ float bx[32], by[32];

    const int t   = threadIdx.x;
    const int bid = blockIdx.x;

    float acc = 0.0f;

    if (bid < NBOX) {
        // ================= BOX ROLE: 299 * prio * sum_c |d| =================
        const int b = bid >> 5;
        const int j = bid & 31;

        if (t < 32) {
            int cx = lm[(b * 68 + 36 + t) * 2 + 0];
            int cy = lm[(b * 68 + 36 + t) * 2 + 1];
            bx[t] = (float)min(max(cx, 0), WDIM - 1);
            by[t] = (float)min(max(cy, 0), HDIM - 1);
        }
        __syncthreads();

        const int cx = (int)bx[j], cy = (int)by[j];
        const int x0 = max(cx - 14, 0), x1 = min(cx + 14, WDIM - 1);
        const int y0 = max(cy - 14, 0), y1 = min(cy + 14, HDIM - 1);
        const int wbox = x1 - x0 + 1;
        const int n    = wbox * (y1 - y0 + 1);

        for (int i = t; i < n; i += THREADS) {
            const int px = x0 + i % wbox;
            const int py = y0 + i / wbox;
            const float pxf = (float)px, pyf = (float)py;

            // Ownership: smallest landmark index whose bbox contains (px,py).
            bool owner = true;
            for (int k = 0; k < j; k++) {
                if (fabsf(pxf - bx[k]) <= 14.f && fabsf(pyf - by[k]) <= 14.f) {
                    owner = false; break;
                }
            }
            if (!owner) continue;

            // Exact priority over all 32 landmarks.
            float e = 0.f, mo = 0.f;
            #pragma unroll 4
            for (int k = 0; k < 32; k++) {
                const float dx = pxf - bx[k];
                const float dy = pyf - by[k];
                const float d2 = fmaf(dx, dx, dy * dy);
                if (d2 < 225.f) {
                    const float v = 1.f - sqrtf(d2) * (1.f / 15.f);
                    if (k < 12) e = fmaxf(e, v);
                    else        mo = fmaxf(mo, v);
                }
            }
            const float prio = fminf(e + mo, 1.f);
            if (prio > 0.f) {
                const int base = b * 3 * HW + py * WDIM + px;
                const float d0 = fabsf(pred[base         ] - targ[base         ]);
                const float d1 = fabsf(pred[base +     HW] - targ[base +     HW]);
                const float d2c = fabsf(pred[base + 2 * HW] - targ[base + 2 * HW]);
                acc += 299.f * prio * (d0 + d1 + d2c);
            }
        }
    } else {
        // ================= STREAM ROLE: pure sum |pred - targ| ==============
        const float4* p4 = reinterpret_cast<const float4*>(pred);
        const float4* q4 = reinterpret_cast<const float4*>(targ);
        const int stride = NSTREAM * THREADS;
        int q = (bid - NBOX) * THREADS + t;

        for (; q + 3 * stride < NQ; q += 4 * stride) {
            const float4 a0 = p4[q];
            const float4 b0 = q4[q];
            const float4 a1 = p4[q + stride];
            const float4 b1 = q4[q + stride];
            const float4 a2 = p4[q + 2 * stride];
            const float4 b2 = q4[q + 2 * stride];
            const float4 a3 = p4[q + 3 * stride];
            const float4 b3 = q4[q + 3 * stride];
            acc += fabsf(a0.x - b0.x) + fabsf(a0.y - b0.y)
                 + fabsf(a0.z - b0.z) + fabsf(a0.w - b0.w);
            acc += fabsf(a1.x - b1.x) + fabsf(a1.y - b1.y)
                 + fabsf(a1.z - b1.z) + fabsf(a1.w - b1.w);
            acc += fabsf(a2.x - b2.x) + fabsf(a2.y - b2.y)
                 + fabsf(a2.z - b2.z) + fabsf(a2.w - b2.w);
            acc += fabsf(a3.x - b3.x) + fabsf(a3.y - b3.y)
                 + fabsf(a3.z - b3.z) + fabsf(a3.w - b3.w);
        }
        for (; q < NQ; q += stride) {
            const float4 a = p4[q];
            const float4 c = q4[q];
            acc += fabsf(a.x - c.x) + fabsf(a.y - c.y)
                 + fabsf(a.z - c.z) + fabsf(a.w - c.w);
        }
    }

    // ---- Block reduction + device-side finalize ----
    #pragma unroll
    for (int off = 16; off; off >>= 1)
        acc += __shfl_down_sync(0xffffffffu, acc, off);

    const int lane32 = t & 31, wid = t >> 5;
    if (lane32 == 0) s_warp[wid] = acc;
    __syncthreads();
    if (wid == 0) {
        acc = (lane32 < 8) ? s_warp[lane32] : 0.0f;
        #pragma unroll
        for (int off = 4; off; off >>= 1)
            acc += __shfl_down_sync(0xffffffffu, acc, off);

        if (lane32 == 0) {
            atomicAdd(&g_acc, (double)acc);
            __threadfence();
            unsigned int ticket = atomicAdd(&g_count, 1u);
            if (ticket == GRID - 1) {
                __threadfence();
                double total = *((volatile double*)&g_acc);
                out[0] = (float)(total * (1.0 / (double)NTOT));
                g_acc   = 0.0;          // clean state for next graph replay
                g_count = 0u;
            }
        }
    }
}

extern "C" void kernel_launch(void* const* d_in, const int* in_sizes, int n_in,
                              void* d_out, int out_size) {
    const float* pred = (const float*)d_in[0];
    const float* targ = (const float*)d_in[1];
    const int*   lm   = (const int*)d_in[2];
    float*       out  = (float*)d_out;

    fused_loss_kernel<<<GRID, THREADS>>>(pred, targ, lm, out);
}

// round 8
// speedup vs baseline: 1.0893x; 1.0893x over previous
#include <cuda_runtime.h>

#define BATCH 16
#define HDIM 512
#define WDIM 512
#define HW (HDIM * WDIM)
#define NTOT (BATCH * 3 * HW)
#define STRIPS_TOT (BATCH * 256)   // 2-row strips, 256 per batch = 4096
#define GRID 592                   // 148 SMs x 4 blocks -> single wave
#define THREADS 256

__device__ double       g_acc;
__device__ unsigned int g_count;

__global__ void __launch_bounds__(THREADS, 4)
fused_loss_kernel(const float* __restrict__ pred,
                  const float* __restrict__ targ,
                  const int*   __restrict__ lm,
                  float*       __restrict__ out) {
    __shared__ float s_warp[8];
    __shared__ float scx[BATCH * 32];
    __shared__ float scy[BATCH * 32];

    const int t      = threadIdx.x;
    const int bid    = blockIdx.x;
    const int lane32 = t & 31;

    // ---- Load ALL landmarks (16 batches x 32) into smem once ----
    for (int i = t; i < BATCH * 32; i += THREADS) {
        const int b = i >> 5, j = i & 31;
        int cx = lm[(b * 68 + 36 + j) * 2 + 0];
        int cy = lm[(b * 68 + 36 + j) * 2 + 1];
        scx[i] = (float)min(max(cx, 0), WDIM - 1);
        scy[i] = (float)min(max(cy, 0), HDIM - 1);
    }
    __syncthreads();

    // Thread -> (row 0/1 of strip, one quad). 128 threads per 512-px row.
    const int   row = t >> 7;
    const int   xq  = (t & 127) << 2;
    const float xf  = (float)xq;

    const int nIter = (STRIPS_TOT - bid + GRID - 1) / GRID;   // 6 or 7
    float acc = 0.0f;

    for (int it = 0; it < nIter; ++it) {
        const int sid = bid + it * GRID;
        const int b   = sid >> 8;
        const int y0  = (sid & 255) << 1;
        const int y   = y0 + row;
        const float yf = (float)y;

        // ---- Issue all 6 float4 pairs for this iteration NOW ----
        const float4* pp = reinterpret_cast<const float4*>(pred + b * 3 * HW + y * WDIM + xq);
        const float4* qq = reinterpret_cast<const float4*>(targ + b * 3 * HW + y * WDIM + xq);
        const float4 p0 = pp[0];          const float4 q0 = qq[0];
        const float4 p1 = pp[HW / 4];     const float4 q1 = qq[HW / 4];
        const float4 p2 = pp[HW / 2];     const float4 q2 = qq[HW / 2];

        // ---- Warp-local landmark mask (no shared, no barrier) ----
        const float cyl = scy[b * 32 + lane32];
        const bool  hit = (cyl >= (float)(y0 - 15)) && (cyl <= (float)(y0 + 16));
        unsigned m = __ballot_sync(0xffffffffu, hit);

        // ---- Weights: walk set bits (~2 avg), runs under load latency ----
        float w0 = 1.f, w1 = 1.f, w2 = 1.f, w3 = 1.f;
        if (m) {
            float e0 = 0.f, e1 = 0.f, e2 = 0.f, e3 = 0.f;
            float f0 = 0.f, f1 = 0.f, f2 = 0.f, f3 = 0.f;
            do {
                const int j = __ffs(m) - 1;
                m &= m - 1;
                const float cx = scx[b * 32 + j];
                const float cy = scy[b * 32 + j];
                const float dy  = yf - cy;
                const float dy2 = dy * dy;
                if (dy2 < 225.f && fabsf(xf + 1.5f - cx) < 18.f) {
                    const float dx0 = xf - cx;
                    const float dx1 = dx0 + 1.f, dx2 = dx0 + 2.f, dx3 = dx0 + 3.f;
                    const float v0 = 1.f - sqrtf(fmaf(dx0, dx0, dy2)) * (1.f / 15.f);
                    const float v1 = 1.f - sqrtf(fmaf(dx1, dx1, dy2)) * (1.f / 15.f);
                    const float v2 = 1.f - sqrtf(fmaf(dx2, dx2, dy2)) * (1.f / 15.f);
                    const float v3 = 1.f - sqrtf(fmaf(dx3, dx3, dy2)) * (1.f / 15.f);
                    if (j < 12) {
                        e0 = fmaxf(e0, v0); e1 = fmaxf(e1, v1);
                        e2 = fmaxf(e2, v2); e3 = fmaxf(e3, v3);
                    } else {
                        f0 = fmaxf(f0, v0); f1 = fmaxf(f1, v1);
                        f2 = fmaxf(f2, v2); f3 = fmaxf(f3, v3);
                    }
                }
            } while (m);
            w0 = fmaf(fminf(e0 + f0, 1.f), 299.f, 1.f);
            w1 = fmaf(fminf(e1 + f1, 1.f), 299.f, 1.f);
            w2 = fmaf(fminf(e2 + f2, 1.f), 299.f, 1.f);
            w3 = fmaf(fminf(e3 + f3, 1.f), 299.f, 1.f);
        }

        // ---- Consume ----
        acc += w0 * fabsf(p0.x - q0.x);
        acc += w1 * fabsf(p0.y - q0.y);
        acc += w2 * fabsf(p0.z - q0.z);
        acc += w3 * fabsf(p0.w - q0.w);
        acc += w0 * fabsf(p1.x - q1.x);
        acc += w1 * fabsf(p1.y - q1.y);
        acc += w2 * fabsf(p1.z - q1.z);
        acc += w3 * fabsf(p1.w - q1.w);
        acc += w0 * fabsf(p2.x - q2.x);
        acc += w1 * fabsf(p2.y - q2.y);
        acc += w2 * fabsf(p2.z - q2.z);
        acc += w3 * fabsf(p2.w - q2.w);
    }

    // ---- Block reduction (8 warps) + device-side finalize ----
    #pragma unroll
    for (int off = 16; off; off >>= 1)
        acc += __shfl_down_sync(0xffffffffu, acc, off);

    const int wid = t >> 5;
    if (lane32 == 0) s_warp[wid] = acc;
    __syncthreads();
    if (wid == 0) {
        acc = (lane32 < 8) ? s_warp[lane32] : 0.0f;
        #pragma unroll
        for (int off = 4; off; off >>= 1)
            acc += __shfl_down_sync(0xffffffffu, acc, off);

        if (lane32 == 0) {
            atomicAdd(&g_acc, (double)acc);
            __threadfence();
            unsigned int ticket = atomicAdd(&g_count, 1u);
            if (ticket == GRID - 1) {
                __threadfence();
                double total = *((volatile double*)&g_acc);
                out[0] = (float)(total * (1.0 / (double)NTOT));
                g_acc   = 0.0;          // clean state for next graph replay
                g_count = 0u;
            }
        }
    }
}

extern "C" void kernel_launch(void* const* d_in, const int* in_sizes, int n_in,
                              void* d_out, int out_size) {
    const float* pred = (const float*)d_in[0];
    const float* targ = (const float*)d_in[1];
    const int*   lm   = (const int*)d_in[2];
    float*       out  = (float*)d_out;

    fused_loss_kernel<<<GRID, THREADS>>>(pred, targ, lm, out);
}

// round 10
// speedup vs baseline: 1.2587x; 1.1556x over previous
#include <cuda_runtime.h>

#define BATCH 16
#define HDIM 512
#define WDIM 512
#define HW (HDIM * WDIM)
#define NTOT (BATCH * 3 * HW)
#define STRIPS_TOT (BATCH * 256)   // 2-row strips
#define GRID 444                   // 148 SMs x 3 blocks -> single wave
#define THREADS 256

__device__ double       g_acc;
__device__ unsigned int g_count;

__device__ __forceinline__ void calc_w(unsigned m,
                                       const float* __restrict__ scx,
                                       const float* __restrict__ scy,
                                       int b, float xf, float yf,
                                       float& w0, float& w1, float& w2, float& w3) {
    w0 = 1.f; w1 = 1.f; w2 = 1.f; w3 = 1.f;
    if (!m) return;
    float e0 = 0.f, e1 = 0.f, e2 = 0.f, e3 = 0.f;
    float f0 = 0.f, f1 = 0.f, f2 = 0.f, f3 = 0.f;
    do {
        const int j = __ffs(m) - 1;
        m &= m - 1;
        const float cx = scx[b * 32 + j];
        const float cy = scy[b * 32 + j];
        const float dy  = yf - cy;
        const float dy2 = dy * dy;
        if (dy2 < 225.f && fabsf(xf + 1.5f - cx) < 18.f) {
            const float dx0 = xf - cx;
            const float dx1 = dx0 + 1.f, dx2 = dx0 + 2.f, dx3 = dx0 + 3.f;
            const float v0 = 1.f - sqrtf(fmaf(dx0, dx0, dy2)) * (1.f / 15.f);
            const float v1 = 1.f - sqrtf(fmaf(dx1, dx1, dy2)) * (1.f / 15.f);
            const float v2 = 1.f - sqrtf(fmaf(dx2, dx2, dy2)) * (1.f / 15.f);
            const float v3 = 1.f - sqrtf(fmaf(dx3, dx3, dy2)) * (1.f / 15.f);
            if (j < 12) {
                e0 = fmaxf(e0, v0); e1 = fmaxf(e1, v1);
                e2 = fmaxf(e2, v2); e3 = fmaxf(e3, v3);
            } else {
                f0 = fmaxf(f0, v0); f1 = fmaxf(f1, v1);
                f2 = fmaxf(f2, v2); f3 = fmaxf(f3, v3);
            }
        }
    } while (m);
    w0 = fmaf(fminf(e0 + f0, 1.f), 299.f, 1.f);
    w1 = fmaf(fminf(e1 + f1, 1.f), 299.f, 1.f);
    w2 = fmaf(fminf(e2 + f2, 1.f), 299.f, 1.f);
    w3 = fmaf(fminf(e3 + f3, 1.f), 299.f, 1.f);
}

// One pipelined step: prefetch (NP*,NQ*) for it+1, build mask(it+1),
// compute weights(it), barrier, consume (CP*,CQ*). Breaks loop when done.
#define STEP(CP0,CQ0,CP1,CQ1,CP2,CQ2, NP0,NQ0,NP1,NQ1,NP2,NQ2)               \
    {                                                                        \
        const int   sid = bid + it * GRID;                                   \
        const int   b   = sid >> 8;                                          \
        const int   y0  = (sid & 255) << 1;                                  \
        const float yf  = (float)(y0 + row);                                 \
        const bool  more = (it + 1 < nIter);                                 \
        if (more) {                                                          \
            const int sid2 = sid + GRID;                                     \
            const int b2   = sid2 >> 8;                                      \
            const int y2   = ((sid2 & 255) << 1) + row;                      \
            const float4* pp = reinterpret_cast<const float4*>(               \
                pred + b2 * 3 * HW + y2 * WDIM + xq);                        \
            const float4* qq = reinterpret_cast<const float4*>(               \
                targ + b2 * 3 * HW + y2 * WDIM + xq);                        \
            NP0 = pp[0];        NQ0 = qq[0];                                 \
            NP1 = pp[HW / 4];   NQ1 = qq[HW / 4];                            \
            NP2 = pp[HW / 2];   NQ2 = qq[HW / 2];                            \
            if (t < 32) {                                                    \
                const float y02 = (float)((sid2 & 255) << 1);                \
                const float cy2 = scy[b2 * 32 + t];                          \
                const bool  hit = (cy2 >= y02 - 15.f) && (cy2 <= y02 + 16.f);\
                const unsigned mm = __ballot_sync(0xffffffffu, hit);         \
                if (t == 0) s_mask[(it + 1) & 1] = mm;                       \
            }                                                                \
        }                                                                    \
        float w0, w1, w2, w3;                                                \
        calc_w(s_mask[it & 1], scx, scy, b, xf, yf, w0, w1, w2, w3);         \
        __syncthreads();                                                     \
        acc += w0 * fabsf(CP0.x - CQ0.x);                                    \
        acc += w1 * fabsf(CP0.y - CQ0.y);                                    \
        acc += w2 * fabsf(CP0.z - CQ0.z);                                    \
        acc += w3 * fabsf(CP0.w - CQ0.w);                                    \
        acc += w0 * fabsf(CP1.x - CQ1.x);                                    \
        acc += w1 * fabsf(CP1.y - CQ1.y);                                    \
        acc += w2 * fabsf(CP1.z - CQ1.z);                                    \
        acc += w3 * fabsf(CP1.w - CQ1.w);                                    \
        acc += w0 * fabsf(CP2.x - CQ2.x);                                    \
        acc += w1 * fabsf(CP2.y - CQ2.y);                                    \
        acc += w2 * fabsf(CP2.z - CQ2.z);                                    \
        acc += w3 * fabsf(CP2.w - CQ2.w);                                    \
        if (!more) break;                                                    \
        ++it;                                                                \
    }

__global__ void __launch_bounds__(THREADS, 3)
fused_loss_kernel(const float* __restrict__ pred,
                  const float* __restrict__ targ,
                  const int*   __restrict__ lm,
                  float*       __restrict__ out) {
    __shared__ float    scx[BATCH * 32];
    __shared__ float    scy[BATCH * 32];
    __shared__ unsigned s_mask[2];
    __shared__ float    s_warp[8];

    const int t   = threadIdx.x;
    const int bid = blockIdx.x;

    // ---- Load ALL landmarks into smem once ----
    for (int i = t; i < BATCH * 32; i += THREADS) {
        const int b = i >> 5, j = i & 31;
        int cx = lm[(b * 68 + 36 + j) * 2 + 0];
        int cy = lm[(b * 68 + 36 + j) * 2 + 1];
        scx[i] = (float)min(max(cx, 0), WDIM - 1);
        scy[i] = (float)min(max(cy, 0), HDIM - 1);
    }
    __syncthreads();

    const int   row = t >> 7;            // 0..1
    const int   xq  = (t & 127) << 2;
    const float xf  = (float)xq;
    const int nIter = (STRIPS_TOT - bid + GRID - 1) / GRID;   // 9 or 10

    // ---- Prologue: mask(0) + loads(0) into buffer A ----
    if (t < 32) {
        const int b0 = bid >> 8;
        const float y00 = (float)((bid & 255) << 1);
        const float cy0 = scy[b0 * 32 + t];
        const bool hit = (cy0 >= y00 - 15.f) && (cy0 <= y00 + 16.f);
        const unsigned m0 = __ballot_sync(0xffffffffu, hit);
        if (t == 0) s_mask[0] = m0;
    }

    float4 Pa0, Qa0, Pa1, Qa1, Pa2, Qa2;
    float4 Pb0, Qb0, Pb1, Qb1, Pb2, Qb2;
    {
        const int b0 = bid >> 8;
        const int y  = ((bid & 255) << 1) + row;
        const float4* pp = reinterpret_cast<const float4*>(pred + b0 * 3 * HW + y * WDIM + xq);
        const float4* qq = reinterpret_cast<const float4*>(targ + b0 * 3 * HW + y * WDIM + xq);
        Pa0 = pp[0];        Qa0 = qq[0];
        Pa1 = pp[HW / 4];   Qa1 = qq[HW / 4];
        Pa2 = pp[HW / 2];   Qa2 = qq[HW / 2];
    }
    __syncthreads();

    float acc = 0.0f;
    int it = 0;
    for (;;) {
        STEP(Pa0, Qa0, Pa1, Qa1, Pa2, Qa2,  Pb0, Qb0, Pb1, Qb1, Pb2, Qb2)
        STEP(Pb0, Qb0, Pb1, Qb1, Pb2, Qb2,  Pa0, Qa0, Pa1, Qa1, Pa2, Qa2)
    }

    // ---- Block reduction (8 warps) + device-side finalize ----
    #pragma unroll
    for (int off = 16; off; off >>= 1)
        acc += __shfl_down_sync(0xffffffffu, acc, off);

    const int lane32 = t & 31, wid = t >> 5;
    if (lane32 == 0) s_warp[wid] = acc;
    __syncthreads();
    if (wid == 0) {
        acc = (lane32 < 8) ? s_warp[lane32] : 0.0f;
        #pragma unroll
        for (int off = 4; off; off >>= 1)
            acc += __shfl_down_sync(0xffffffffu, acc, off);

        if (lane32 == 0) {
            atomicAdd(&g_acc, (double)acc);
            __threadfence();
            unsigned int ticket = atomicAdd(&g_count, 1u);
            if (ticket == GRID - 1) {
                __threadfence();
                double total = *((volatile double*)&g_acc);
                out[0] = (float)(total * (1.0 / (double)NTOT));
                g_acc   = 0.0;          // clean state for next graph replay
                g_count = 0u;
            }
        }
    }
}

extern "C" void kernel_launch(void* const* d_in, const int* in_sizes, int n_in,
                              void* d_out, int out_size) {
    const float* pred = (const float*)d_in[0];
    const float* targ = (const float*)d_in[1];
    const int*   lm   = (const int*)d_in[2];
    float*       out  = (float*)d_out;

    fused_loss_kernel<<<GRID, THREADS>>>(pred, targ, lm, out);
}